// round 16
// baseline (speedup 1.0000x reference)
#include <cuda_runtime.h>
#include <cuda_bf16.h>
#include <cuda_fp16.h>
#include <math.h>

// ---------------- problem constants ----------------
#define BATCH   4
#define TEXT    64
#define NTOK    321
#define DIM     1024
#define HEADS   16
#define HD      64
#define MLPD    4096
#define NPATCH  256
#define PCH     768
#define TDIM    256
#define NLAYERS 2
#define VOCAB   50000
#define IMG     256
#define MROWS   (BATCH*NTOK) // 1284
#define DD      (DIM*DIM)
#define NPAD    384

typedef unsigned short u16;
typedef unsigned int u32;

// ---------------- scratch ----------------
__device__ float g_x  [MROWS*DIM];
__device__ float g_t1raw[BATCH*DIM];
__device__ float g_t1 [BATCH*DIM];
__device__ float g_mod[BATCH*6*DIM];
__device__ float g_ropec[NPAD*HD];
__device__ float g_ropes[NPAD*HD];

// fp16 activation buffers
__device__ __align__(16) u16 g_qkv_h[MROWS*3*DIM];
__device__ __align__(16) u16 g_xn_h[MROWS*DIM];
__device__ __align__(16) u16 g_hh  [MROWS*MLPD];
__device__ __align__(16) u16 g_o_h [MROWS*DIM];
__device__ __align__(16) u16 g_im_h[BATCH*NPATCH*PCH];

// fp16 weights
#define OFF_PATCH 0
#define SZ_PATCH  (DIM*PCH)
#define OFF_QKV   (OFF_PATCH+SZ_PATCH)
#define SZ_QKV    (NLAYERS*3*DD)
#define OFF_WO    (OFF_QKV+SZ_QKV)
#define SZ_WO     (NLAYERS*DD)
#define OFF_WM1   (OFF_WO+SZ_WO)
#define SZ_WM     (NLAYERS*MLPD*DIM)
#define OFF_WM2   (OFF_WM1+SZ_WM)
#define OFF_FIN   (OFF_WM2+SZ_WM)
#define SZ_FIN    (PCH*DIM)
#define WTOTAL    (OFF_FIN+SZ_FIN)
__device__ __align__(16) u16 g_w_h[WTOTAL];

// ---------------- helpers ----------------
__device__ __forceinline__ void store_h(float v, u16* h, long idx) {
    h[idx] = __half_as_ushort(__float2half_rn(v));
}
__device__ __forceinline__ u16 fp16_hi(float v) {
    return __half_as_ushort(__float2half_rn(v));
}
__device__ __forceinline__ float h2f(u16 v) {
    return __half2float(__ushort_as_half(v));
}

// ---------------- RoPE tables ----------------
__global__ void rope_table_kernel() {
    int idx = blockIdx.x * blockDim.x + threadIdx.x;
    if (idx >= NPAD * HD) return;
    int d = idx & 63, n = idx >> 6;
    double fr = pow(10000.0, -((double)(d & 31)) / 32.0);
    double a = (double)n * fr;
    g_ropec[idx] = (float)cos(a);
    g_ropes[idx] = (float)sin(a);
}

// ---------------- mega weight conversion ----------------
__global__ void cvt_all_kernel(const float* __restrict__ Wp,
                               const float* __restrict__ Wq, const float* __restrict__ Wk,
                               const float* __restrict__ Wv, const float* __restrict__ Wo,
                               const float* __restrict__ Wm1, const float* __restrict__ Wm2,
                               const float* __restrict__ Wf) {
    long q = (long)blockIdx.x * blockDim.x + threadIdx.x;
    long nq = WTOTAL / 4;
    if (q >= nq) return;
    long idx = q * 4;
    const float* src;
    long sofs;
    if (idx < OFF_QKV) { src = Wp; sofs = idx; }
    else if (idx < OFF_WO) {
        long rel = idx - OFF_QKV;
        long l = rel / (3 * (long)DD);
        long r2 = rel % (3 * (long)DD);
        long which = r2 / DD;
        long inner = r2 % DD;
        src = (which == 0) ? Wq : (which == 1) ? Wk : Wv;
        sofs = l * DD + inner;
    } else if (idx < OFF_WM1) { src = Wo; sofs = idx - OFF_WO; }
    else if (idx < OFF_WM2) { src = Wm1; sofs = idx - OFF_WM1; }
    else if (idx < OFF_FIN) { src = Wm2; sofs = idx - OFF_WM2; }
    else { src = Wf; sofs = idx - OFF_FIN; }
    float4 v = *(const float4*)(src + sofs);
    ushort4 h;
    h.x = fp16_hi(v.x); h.y = fp16_hi(v.y); h.z = fp16_hi(v.z); h.w = fp16_hi(v.w);
    *(ushort4*)(g_w_h + idx) = h;
}

// ---------------- embeddings ----------------
__global__ void embed_text_cls_kernel(const int* __restrict__ tokens,
                                      const float* __restrict__ W_tok,
                                      const float* __restrict__ pos_text,
                                      const float* __restrict__ cls_tok) {
    int idx = blockIdx.x * blockDim.x + threadIdx.x;
    if (idx >= BATCH * 65 * DIM) return;
    int d = idx % DIM;
    int t = (idx / DIM) % 65;
    int b = idx / (DIM * 65);
    float v;
    if (t < TEXT) {
        int tok = tokens[b * TEXT + t];
        v = W_tok[(long)d * VOCAB + tok] + pos_text[t * DIM + d];
    } else v = cls_tok[d];
    g_x[(b * NTOK + t) * DIM + d] = v;
}

__global__ void im2col_kernel(const float* __restrict__ img) {
    int idx = blockIdx.x * blockDim.x + threadIdx.x;
    if (idx >= BATCH * NPATCH * PCH) return;
    int c = idx % PCH;
    int p = (idx / PCH) % NPATCH;
    int b = idx / (PCH * NPATCH);
    int ch = c / 256;
    int pr = (c / 16) % 16;
    int pc = c % 16;
    int hp = p / 16, wp = p % 16;
    float v = img[((b * 3 + ch) * IMG + hp * 16 + pr) * IMG + wp * 16 + pc];
    store_h(v, g_im_h, idx);
}

// ---------------- timestep embedding ----------------
__global__ void ts_a_kernel(const int* __restrict__ tsteps,
                            const float* __restrict__ W_t1, const float* __restrict__ b_t1) {
    __shared__ float sraw[TDIM];
    int b = blockIdx.y;
    int tid = threadIdx.x, lane = tid & 31, warp = tid >> 5;
    {
        int j = tid & 127;
        float f = expf(-logf(10000.0f) * (float)j / 128.0f);
        float a = (float)tsteps[b] * f;
        sraw[tid] = (tid < 128) ? cosf(a) : sinf(a);
    }
    __syncthreads();
#pragma unroll
    for (int r = 0; r < 4; r++) {
        int d = blockIdx.x * 32 + warp * 4 + r;
        const float4* w = (const float4*)(W_t1 + (long)d * TDIM);
        const float4* a4 = (const float4*)sraw;
        float s = 0.f;
#pragma unroll
        for (int it = 0; it < 2; it++) {
            float4 wv = w[it * 32 + lane];
            float4 av = a4[it * 32 + lane];
            s += wv.x * av.x + wv.y * av.y + wv.z * av.z + wv.w * av.w;
        }
#pragma unroll
        for (int o = 16; o > 0; o >>= 1) s += __shfl_xor_sync(0xffffffffu, s, o);
        if (lane == 0) {
            s += b_t1[d];
            g_t1raw[b * DIM + d] = s / (1.0f + expf(-s));
        }
    }
}

__global__ void ts_b_kernel(const float* __restrict__ W_t2, const float* __restrict__ b_t2) {
    int b = blockIdx.y;
    int tid = threadIdx.x, lane = tid & 31, warp = tid >> 5;
    const float4* a4 = (const float4*)(g_t1raw + b * DIM);
#pragma unroll
    for (int r = 0; r < 4; r++) {
        int d = blockIdx.x * 32 + warp * 4 + r;
        const float4* w = (const float4*)(W_t2 + (long)d * DIM);
        float s = 0.f;
#pragma unroll
        for (int it = 0; it < 8; it++) {
            float4 wv = w[it * 32 + lane];
            float4 av = a4[it * 32 + lane];
            s += wv.x * av.x + wv.y * av.y + wv.z * av.z + wv.w * av.w;
        }
#pragma unroll
        for (int o = 16; o > 0; o >>= 1) s += __shfl_xor_sync(0xffffffffu, s, o);
        if (lane == 0) {
            s += b_t2[d];
            g_t1[b * DIM + d] = s / (1.0f + expf(-s));
        }
    }
}

// ---------------- adaLN modulation ----------------
__global__ void ada_kernel(const float* __restrict__ W, const float* __restrict__ bias) {
    int tid = threadIdx.x, lane = tid & 31, warp = tid >> 5;
#pragma unroll
    for (int r = 0; r < 4; r++) {
        int row = blockIdx.x * 32 + warp * 4 + r;
        const float4* w = (const float4*)(W + (long)row * DIM);
        float a0 = 0.f, a1 = 0.f, a2 = 0.f, a3 = 0.f;
#pragma unroll
        for (int it = 0; it < 8; it++) {
            float4 wv = w[it * 32 + lane];
            float4 v0 = *(const float4*)&g_t1[0 * DIM + it * 128 + lane * 4];
            float4 v1 = *(const float4*)&g_t1[1 * DIM + it * 128 + lane * 4];
            float4 v2 = *(const float4*)&g_t1[2 * DIM + it * 128 + lane * 4];
            float4 v3 = *(const float4*)&g_t1[3 * DIM + it * 128 + lane * 4];
            a0 += wv.x * v0.x + wv.y * v0.y + wv.z * v0.z + wv.w * v0.w;
            a1 += wv.x * v1.x + wv.y * v1.y + wv.z * v1.z + wv.w * v1.w;
            a2 += wv.x * v2.x + wv.y * v2.y + wv.z * v2.z + wv.w * v2.w;
            a3 += wv.x * v3.x + wv.y * v3.y + wv.z * v3.z + wv.w * v3.w;
        }
#pragma unroll
        for (int o = 16; o > 0; o >>= 1) {
            a0 += __shfl_xor_sync(0xffffffffu, a0, o);
            a1 += __shfl_xor_sync(0xffffffffu, a1, o);
            a2 += __shfl_xor_sync(0xffffffffu, a2, o);
            a3 += __shfl_xor_sync(0xffffffffu, a3, o);
        }
        if (lane == 0) {
            float bs = bias[row];
            g_mod[0 * 6 * DIM + row] = a0 + bs;
            g_mod[1 * 6 * DIM + row] = a1 + bs;
            g_mod[2 * 6 * DIM + row] = a2 + bs;
            g_mod[3 * 6 * DIM + row] = a3 + bs;
        }
    }
}

// ---------------- MMA primitives ----------------
__device__ __forceinline__ void cp16(u32 dst, const void* src, bool valid) {
    int sz = valid ? 16 : 0;
    asm volatile("cp.async.ca.shared.global [%0], [%1], 16, %2;\n" :: "r"(dst), "l"(src), "r"(sz));
}
__device__ __forceinline__ void cp_commit() { asm volatile("cp.async.commit_group;\n"); }
__device__ __forceinline__ void cp_wait0() { asm volatile("cp.async.wait_group 0;\n"); }
__device__ __forceinline__ void cp_wait1() { asm volatile("cp.async.wait_group 1;\n"); }

__device__ __forceinline__ void ldsm4(u32& r0, u32& r1, u32& r2, u32& r3, u32 addr) {
    asm volatile("ldmatrix.sync.aligned.m8n8.x4.shared.b16 {%0,%1,%2,%3}, [%4];\n"
                 : "=r"(r0), "=r"(r1), "=r"(r2), "=r"(r3) : "r"(addr));
}
__device__ __forceinline__ void ldsm4t(u32& r0, u32& r1, u32& r2, u32& r3, u32 addr) {
    asm volatile("ldmatrix.sync.aligned.m8n8.x4.trans.shared.b16 {%0,%1,%2,%3}, [%4];\n"
                 : "=r"(r0), "=r"(r1), "=r"(r2), "=r"(r3) : "r"(addr));
}

__device__ __forceinline__ void mma16816h(float* c, const u32* a, const u32* b) {
    asm volatile(
        "mma.sync.aligned.m16n8k16.row.col.f32.f16.f16.f32 "
        "{%0,%1,%2,%3}, {%4,%5,%6,%7}, {%8,%9}, {%0,%1,%2,%3};\n"
        : "+f"(c[0]), "+f"(c[1]), "+f"(c[2]), "+f"(c[3])
        : "r"(a[0]), "r"(a[1]), "r"(a[2]), "r"(a[3]), "r"(b[0]), "r"(b[1]));
}

// ---------------- tensor-core GEMM: fp16 x fp16, 64x128 tile ----------------
// epi: 0 = fp32 C (+bias); 1 = gelu -> fp16; 2 = fp32 C += gate*acc
// epi 3: patch embed -> g_x (bias = pos_img); epi 4: final scatter; epi 5: plain fp16 store
__global__ __launch_bounds__(256) void mma_gemm7_kernel(
        const u16* __restrict__ Ah, const u16* __restrict__ Wh,
        float* __restrict__ C, u16* __restrict__ Oh,
        int M, int Nt, int K,
        const float* __restrict__ bias,
        const float* __restrict__ gate, int gate_ofs, int epi) {
    constexpr u32 RS  = 144;
    constexpr u32 SA  = 64 * RS;
    constexpr u32 SW  = 128 * RS;
    constexpr u32 WHI = SA;
    constexpr u32 STG = SA + SW;

    extern __shared__ char smem[];
    u32 sbase = (u32)__cvta_generic_to_shared(smem);

    int tid = threadIdx.x, lane = tid & 31, warp = tid >> 5;
    int wm = warp >> 2, wn = warp & 3;
    int row0 = blockIdx.y * 64, col0 = blockIdx.x * 128;

    float acc[2][4][4];
#pragma unroll
    for (int i = 0; i < 2; i++)
#pragma unroll
        for (int j = 0; j < 4; j++)
#pragma unroll
            for (int t = 0; t < 4; t++) acc[i][j][t] = 0.0f;

    u32 a_off = (lane & 15) * RS + (lane >> 4) * 16;
    u32 w_off = (((lane >> 4) & 1) * 8 + (lane & 7)) * RS + ((lane >> 3) & 1) * 16;

    auto stage_load = [&](int stage, int k0) {
        u32 sb = sbase + stage * STG;
#pragma unroll
        for (int c0 = 0; c0 < 1536; c0 += 256) {
            int c = c0 + tid;
            const u16* src;
            u32 dofs;
            int idx;
            bool isA;
            if (c < 512) { src = Ah; dofs = 0;   idx = c;       isA = true; }
            else         { src = Wh; dofs = WHI; idx = c - 512; isA = false; }
            int row = idx >> 3, q = idx & 7;
            long grow = isA ? (long)(row0 + row) : (long)(col0 + row);
            const void* s = src + grow * K + k0 + q * 8;
            cp16(sb + dofs + row * RS + q * 16, s, !isA || grow < M);
        }
    };

    int KT = K >> 6;
    stage_load(0, 0);
    cp_commit();

    for (int kt = 0; kt < KT; kt++) {
        if (kt + 1 < KT) {
            stage_load((kt + 1) & 1, (kt + 1) << 6);
            cp_commit();
            cp_wait1();
        } else {
            cp_wait0();
        }
        __syncthreads();

        u32 sb = sbase + (u32)(kt & 1) * STG;
#pragma unroll
        for (int s = 0; s < 4; s++) {
            u32 ah[2][4];
#pragma unroll
            for (int mt = 0; mt < 2; mt++) {
                u32 aaddr = sb + (wm * 32 + mt * 16) * RS + s * 32 + a_off;
                ldsm4(ah[mt][0], ah[mt][1], ah[mt][2], ah[mt][3], aaddr);
            }
            u32 bh[2][4];
#pragma unroll
            for (int ntp = 0; ntp < 2; ntp++) {
                u32 waddr = sb + WHI + (wn * 32 + ntp * 16) * RS + s * 32 + w_off;
                ldsm4(bh[ntp][0], bh[ntp][1], bh[ntp][2], bh[ntp][3], waddr);
            }
#pragma unroll
            for (int mt = 0; mt < 2; mt++)
#pragma unroll
                for (int nt = 0; nt < 4; nt++) {
                    const u32* Bh = &bh[nt >> 1][(nt & 1) * 2];
                    mma16816h(acc[mt][nt], ah[mt], Bh);
                }
        }
        __syncthreads();
    }

#pragma unroll
    for (int mt = 0; mt < 2; mt++)
#pragma unroll
        for (int nt = 0; nt < 4; nt++)
#pragma unroll
            for (int half = 0; half < 2; half++) {
                int row = row0 + wm * 32 + mt * 16 + (lane >> 2) + half * 8;
                if (row >= M) continue;
#pragma unroll
                for (int jj = 0; jj < 2; jj++) {
                    int col = col0 + wn * 32 + nt * 8 + (lane & 3) * 2 + jj;
                    float v = acc[mt][nt][half * 2 + jj];
                    long idx = (long)row * Nt + col;
                    if (epi == 0) {
                        if (bias) v += bias[col];
                        C[idx] = v;
                    } else if (epi == 1) {
                        float gu = 0.5f * v * (1.0f + erff(v * 0.70710678118654752f));
                        store_h(gu, Oh, idx);
                    } else if (epi == 2) {
                        int b = row / NTOK;
                        C[idx] += gate[b * 6 * DIM + gate_ofs + col] * v;
                    } else if (epi == 3) {
                        int b = row >> 8, p = row & 255;
                        C[(long)(b * NTOK + 65 + p) * DIM + col] = v + bias[p * DIM + col];
                    } else if (epi == 4) {
                        int b = row >> 8, p = row & 255;
                        int ch = col >> 8, pr = (col >> 4) & 15, pc = col & 15;
                        int hp = p >> 4, wp = p & 15;
                        C[((long)(b * 3 + ch) * IMG + hp * 16 + pr) * IMG + wp * 16 + pc] = v + bias[col];
                    } else {
                        store_h(v, Oh, idx);
                    }
                }
            }
}

// ---------------- layernorm + adaLN modulation ----------------
__global__ void ln_mod_kernel(const float* __restrict__ x,
                              u16* __restrict__ outh,
                              const float* __restrict__ g, const float* __restrict__ beta,
                              const float* __restrict__ mod, int sh_ofs, int sc_ofs) {
    int row = blockIdx.x;
    int b = row / NTOK;
    const float* xr = x + (long)row * DIM;
    __shared__ float red[256];
    int tid = threadIdx.x;
    float local[4];
    float s = 0.0f;
#pragma unroll
    for (int i = 0; i < 4; i++) { local[i] = xr[tid + i * 256]; s += local[i]; }
    red[tid] = s; __syncthreads();
    for (int o = 128; o > 0; o >>= 1) { if (tid < o) red[tid] += red[tid + o]; __syncthreads(); }
    float mean = red[0] * (1.0f / DIM);
    __syncthreads();
    float s2 = 0.0f;
#pragma unroll
    for (int i = 0; i < 4; i++) { float d = local[i] - mean; s2 += d * d; }
    red[tid] = s2; __syncthreads();
    for (int o = 128; o > 0; o >>= 1) { if (tid < o) red[tid] += red[tid + o]; __syncthreads(); }
    float inv = rsqrtf(red[0] * (1.0f / DIM) + 1e-5f);
#pragma unroll
    for (int i = 0; i < 4; i++) {
        int d = tid + i * 256;
        float v = (local[i] - mean) * inv * g[d] + beta[d];
        v = v * (1.0f + mod[b * 6 * DIM + sc_ofs + d]) + mod[b * 6 * DIM + sh_ofs + d];
        store_h(v, outh, (long)row * DIM + d);
    }
}

__global__ void final_ln_kernel(const float* __restrict__ g, const float* __restrict__ beta) {
    int p = blockIdx.x % NPATCH;
    int b = blockIdx.x / NPATCH;
    const float* xr = g_x + (long)(b * NTOK + 65 + p) * DIM;
    __shared__ float red[256];
    int tid = threadIdx.x;
    float local[4];
    float s = 0.0f;
#pragma unroll
    for (int i = 0; i < 4; i++) { local[i] = xr[tid + i * 256]; s += local[i]; }
    red[tid] = s; __syncthreads();
    for (int o = 128; o > 0; o >>= 1) { if (tid < o) red[tid] += red[tid + o]; __syncthreads(); }
    float mean = red[0] * (1.0f / DIM);
    __syncthreads();
    float s2 = 0.0f;
#pragma unroll
    for (int i = 0; i < 4; i++) { float d = local[i] - mean; s2 += d * d; }
    red[tid] = s2; __syncthreads();
    for (int o = 128; o > 0; o >>= 1) { if (tid < o) red[tid] += red[tid + o]; __syncthreads(); }
    float inv = rsqrtf(red[0] * (1.0f / DIM) + 1e-5f);
#pragma unroll
    for (int i = 0; i < 4; i++) {
        int d = tid + i * 256;
        float v = (local[i] - mean) * inv * g[d] + beta[d];
        store_h(v, g_xn_h, (long)blockIdx.x * DIM + d);
    }
}

// ---------------- flash attention v4: fp16 QKV, single-term QK + AV HMMA ----------------
#define FAB_QS   0                        // q fp32 stage [64][68] = 17408 B
#define FAB_KS   (64*68*4)                // k fp32 stage [32][68] = 8704 B
#define FAB_QH   (FAB_KS + 32*68*4)       // 26112: q fp16, 64 x 72 u16
#define FAB_KH   (FAB_QH + 64*144)        // 35328: k/v fp16, 32 x 72 u16
#define FAB_S    (FAB_KH + 32*144)        // 39936: S fp32 [64][352]
#define FAB_P    (FAB_S + 64*352*4)       // 130048: P fp16 [64][360]
#define FAB_TOT  (FAB_P + 64*360*2)       // 176128

__global__ __launch_bounds__(256) void flash_attn4_kernel(
        const u16* __restrict__ qkvh, u16* __restrict__ oh) {
    extern __shared__ char smraw[];
    u32 sbase = (u32)__cvta_generic_to_shared(smraw);
    float* qs = (float*)(smraw + FAB_QS);
    float* ks = (float*)(smraw + FAB_KS);
    float* S  = (float*)(smraw + FAB_S);
    u16* qh16 = (u16*)(smraw + FAB_QH);
    u16* kh16 = (u16*)(smraw + FAB_KH);
    u16* p16  = (u16*)(smraw + FAB_P);

    int tile = blockIdx.x;
    int bh = blockIdx.y;
    int h = bh % HEADS, b = bh / HEADS;
    int tid = threadIdx.x, lane = tid & 31, warp = tid >> 5;

    // ---- load Q (fp16 -> fp32 stage) ----
    for (int i = tid; i < 64 * 64; i += 256) {
        int r = i >> 6, d = i & 63;
        int grow = tile * 64 + r;
        float v = 0.f;
        if (grow < NTOK) v = h2f(qkvh[(long)(b * NTOK + grow) * 3072 + h * HD + d]);
        qs[r * 68 + d] = v;
    }
    __syncthreads();
    // ---- RoPE Q -> fp16 ----
#pragma unroll
    for (int t = 0; t < 16; t++) {
        int i = tid + t * 256;
        int r = i >> 6, d = i & 63;
        int grow = tile * 64 + r;
        float x = qs[r * 68 + d];
        float pr = (d < 32) ? -qs[r * 68 + 2 * d + 1] : qs[r * 68 + 2 * (d - 32)];
        float v = x * g_ropec[grow * HD + d] + pr * g_ropes[grow * HD + d];
        qh16[r * 72 + d] = __half_as_ushort(__float2half_rn(v));
    }
    __syncthreads();

    // ---- QK^T via HMMA: warps 4x2 over 64x32 chunk ----
    int wm = warp >> 1, wn = warp & 1;
    u32 a_off = (lane & 15) * 144 + (lane >> 4) * 16;
    u32 w_off = (((lane >> 4) & 1) * 8 + (lane & 7)) * 144 + ((lane >> 3) & 1) * 16;

    for (int c = 0; c < 11; c++) {
        for (int i = tid; i < 32 * 64; i += 256) {
            int j = i >> 6, d = i & 63;
            int krow = c * 32 + j;
            float v = 0.f;
            if (krow < NTOK) v = h2f(qkvh[(long)(b * NTOK + krow) * 3072 + DIM + h * HD + d]);
            ks[j * 68 + d] = v;
        }
        __syncthreads();
#pragma unroll
        for (int t = 0; t < 8; t++) {
            int i = tid + t * 256;
            int j = i >> 6, d = i & 63;
            float x = ks[j * 68 + d];
            float pr = (d < 32) ? -ks[j * 68 + 2 * d + 1] : ks[j * 68 + 2 * (d - 32)];
            int krow = c * 32 + j;
            float v = x * g_ropec[krow * HD + d] + pr * g_ropes[krow * HD + d];
            kh16[j * 72 + d] = __half_as_ushort(__float2half_rn(v));
        }
        __syncthreads();

        float accq[2][4];
#pragma unroll
        for (int n = 0; n < 2; n++)
#pragma unroll
            for (int t = 0; t < 4; t++) accq[n][t] = 0.f;
#pragma unroll
        for (int s = 0; s < 4; s++) {
            u32 ah[4], bk[4];
            u32 aaddr = sbase + FAB_QH + wm * 16 * 144 + s * 32 + a_off;
            ldsm4(ah[0], ah[1], ah[2], ah[3], aaddr);
            u32 baddr = sbase + FAB_KH + wn * 16 * 144 + s * 32 + w_off;
            ldsm4(bk[0], bk[1], bk[2], bk[3], baddr);
            mma16816h(accq[0], ah, bk + 0);
            mma16816h(accq[1], ah, bk + 2);
        }
#pragma unroll
        for (int nt = 0; nt < 2; nt++)
#pragma unroll
            for (int half = 0; half < 2; half++)
#pragma unroll
                for (int jj = 0; jj < 2; jj++) {
                    int row = wm * 16 + (lane >> 2) + half * 8;
                    int colL = wn * 16 + nt * 8 + (lane & 3) * 2 + jj;
                    int kg = c * 32 + colL;
                    S[row * 352 + c * 32 + colL] =
                        (kg < NTOK) ? accq[nt][half * 2 + jj] * 0.125f : -1e30f;
                }
        __syncthreads();
    }

    // ---- softmax; write P fp16 with invr folded ----
#pragma unroll
    for (int r8 = 0; r8 < 8; r8++) {
        float* Sr = &S[(warp * 8 + r8) * 352];
        float mx = -1e30f;
#pragma unroll
        for (int k = 0; k < 11; k++) mx = fmaxf(mx, Sr[lane + k * 32]);
#pragma unroll
        for (int o = 16; o > 0; o >>= 1) mx = fmaxf(mx, __shfl_xor_sync(0xffffffffu, mx, o));
        float sum = 0.f;
        float ev[11];
#pragma unroll
        for (int k = 0; k < 11; k++) {
            ev[k] = __expf(Sr[lane + k * 32] - mx);
            sum += ev[k];
        }
#pragma unroll
        for (int o = 16; o > 0; o >>= 1) sum += __shfl_xor_sync(0xffffffffu, sum, o);
        float inv = 1.0f / sum;
        u16* Pr = &p16[(warp * 8 + r8) * 360];
#pragma unroll
        for (int k = 0; k < 11; k++)
            Pr[lane + k * 32] = __half_as_ushort(__float2half_rn(ev[k] * inv));
    }
    __syncthreads();

    // ---- AV via HMMA: warps 4x2 (wm rows 16, wn cols 32) ----
    float accv[4][4];
#pragma unroll
    for (int n = 0; n < 4; n++)
#pragma unroll
        for (int t = 0; t < 4; t++) accv[n][t] = 0.f;

    u32 p_off = (lane & 15) * 720 + (lane >> 4) * 16;

    for (int c = 0; c < 11; c++) {
        // V: raw fp16 copy (no conversion)
        for (int i = tid; i < 32 * 32; i += 256) {
            int j = i >> 5, dq = (i & 31) * 2;
            int vrow = c * 32 + j;
            u32 v = 0;
            if (vrow < NTOK)
                v = *(const u32*)&qkvh[(long)(b * NTOK + vrow) * 3072 + 2 * DIM + h * HD + dq];
            *(u32*)&kh16[j * 72 + dq] = v;
        }
        __syncthreads();
#pragma unroll
        for (int s = 0; s < 2; s++) {
            u32 pa[4];
            u32 paddr = sbase + FAB_P + (u32)(wm * 16) * 720 + (u32)(c * 32 + s * 16) * 2 + p_off;
            ldsm4(pa[0], pa[1], pa[2], pa[3], paddr);
#pragma unroll
            for (int nn = 0; nn < 2; nn++) {
                u32 vb[4];
                u32 vaddr = sbase + FAB_KH + (u32)(s * 16 + (lane & 15)) * 144
                            + (u32)(wn * 32 + nn * 16 + (lane >> 4) * 8) * 2;
                ldsm4t(vb[0], vb[1], vb[2], vb[3], vaddr);
                mma16816h(accv[nn * 2 + 0], pa, vb + 0);
                mma16816h(accv[nn * 2 + 1], pa, vb + 2);
            }
        }
        __syncthreads();
    }

    // ---- epilogue ----
#pragma unroll
    for (int nt = 0; nt < 4; nt++)
#pragma unroll
        for (int half = 0; half < 2; half++) {
            int rowL = wm * 16 + (lane >> 2) + half * 8;
            int grow = tile * 64 + rowL;
            if (grow >= NTOK) continue;
#pragma unroll
            for (int jj = 0; jj < 2; jj++) {
                int col = wn * 32 + nt * 8 + (lane & 3) * 2 + jj;
                store_h(accv[nt][half * 2 + jj], oh,
                        (long)(b * NTOK + grow) * DIM + h * HD + col);
            }
        }
}

// ---------------- host launch ----------------
static void* symaddr_raw(const void* sym) {
    void* p = nullptr;
    cudaGetSymbolAddress(&p, sym);
    return p;
}

#define SMEMG7 (2 * (64 * 144 + 128 * 144))   // 55296

extern "C" void kernel_launch(void* const* d_in, const int* in_sizes, int n_in,
                              void* d_out, int out_size) {
    const float* noisy    = (const float*)d_in[0];
    const int*   tokens   = (const int*)  d_in[1];
    const int*   tsteps   = (const int*)  d_in[2];
    const float* W_tok    = (const float*)d_in[3];
    const float* pos_text = (const float*)d_in[4];
    const float* W_patch  = (const float*)d_in[5];
    const float* pos_img  = (const float*)d_in[6];
    const float* cls_tok  = (const float*)d_in[7];
    const float* W_t1     = (const float*)d_in[8];
    const float* b_t1     = (const float*)d_in[9];
    const float* W_t2     = (const float*)d_in[10];
    const float* b_t2     = (const float*)d_in[11];
    const float* ln1_g    = (const float*)d_in[12];
    const float* ln1_b    = (const float*)d_in[13];
    const float* Wq       = (const float*)d_in[14];
    const float* Wk       = (const float*)d_in[15];
    const float* Wv       = (const float*)d_in[16];
    const float* Wo       = (const float*)d_in[17];
    const float* ln2_g    = (const float*)d_in[18];
    const float* ln2_b    = (const float*)d_in[19];
    const float* Wm1      = (const float*)d_in[20];
    const float* Wm2      = (const float*)d_in[21];
    const float* Wada     = (const float*)d_in[22];
    const float* b_ada    = (const float*)d_in[23];
    const float* fn_g     = (const float*)d_in[24];
    const float* fn_b     = (const float*)d_in[25];
    const float* W_final  = (const float*)d_in[26];
    const float* b_final  = (const float*)d_in[27];
    float* out = (float*)d_out;

    float* p_x    = (float*)symaddr_raw(g_x);
    float* p_mod  = (float*)symaddr_raw(g_mod);
    u16* p_wh     = (u16*)symaddr_raw(g_w_h);
    u16* p_qkvh   = (u16*)symaddr_raw(g_qkv_h);
    u16* p_xnh    = (u16*)symaddr_raw(g_xn_h);
    u16* p_hh     = (u16*)symaddr_raw(g_hh);
    u16* p_oh     = (u16*)symaddr_raw(g_o_h);
    u16* p_imh    = (u16*)symaddr_raw(g_im_h);

    static bool attr_set = false;
    if (!attr_set) {
        cudaFuncSetAttribute(mma_gemm7_kernel, cudaFuncAttributeMaxDynamicSharedMemorySize, SMEMG7);
        cudaFuncSetAttribute(flash_attn4_kernel, cudaFuncAttributeMaxDynamicSharedMemorySize, FAB_TOT);
        attr_set = true;
    }

    im2col_kernel<<<(BATCH * NPATCH * PCH + 255) / 256, 256>>>(noisy);               // 0
    cvt_all_kernel<<<(WTOTAL / 4 + 511) / 512, 512>>>(W_patch, Wq, Wk, Wv, Wo, Wm1, Wm2, W_final); // 1
    ts_a_kernel<<<dim3(32, BATCH), 256>>>(tsteps, W_t1, b_t1);                        // 2
    // patch projection fused with pos_img add -> g_x (epi 3)
    mma_gemm7_kernel<<<dim3(DIM / 128, 16), 256, SMEMG7>>>(
        p_imh, p_wh + OFF_PATCH,
        p_x, nullptr, BATCH * NPATCH, DIM, PCH, pos_img, nullptr, 0, 3);              // 3
    rope_table_kernel<<<(NPAD * HD + 255) / 256, 256>>>();                            // 4
    ts_b_kernel<<<dim3(32, BATCH), 256>>>(W_t2, b_t2);                                // 5
    embed_text_cls_kernel<<<(BATCH * 65 * DIM + 255) / 256, 256>>>(tokens, W_tok, pos_text, cls_tok);

    int gy = (MROWS + 63) / 64;   // 21

    for (int l = 0; l < NLAYERS; l++) {
        long wqkv_o = OFF_QKV + (long)l * 3 * DD;
        long wo_o   = OFF_WO + (long)l * DD;
        long wm1_o  = OFF_WM1 + (long)l * MLPD * DIM;
        long wm2_o  = OFF_WM2 + (long)l * DIM * MLPD;
        const float* Wada_l = Wada + (long)l * 6 * DIM * DIM;
        const float* bada_l = b_ada + (long)l * 6 * DIM;

        ada_kernel<<<192, 256>>>(Wada_l, bada_l);

        ln_mod_kernel<<<MROWS, 256>>>(p_x, p_xnh, ln1_g + l * DIM, ln1_b + l * DIM,
                                      p_mod, 0, DIM);

        // QKV projection -> fp16 (epi 5)
        mma_gemm7_kernel<<<dim3(3 * DIM / 128, gy), 256, SMEMG7>>>(
            p_xnh, p_wh + wqkv_o, nullptr, p_qkvh,
            MROWS, 3 * DIM, DIM, nullptr, nullptr, 0, 5);

        flash_attn4_kernel<<<dim3(6, BATCH * HEADS), 256, FAB_TOT>>>(p_qkvh, p_oh);

        mma_gemm7_kernel<<<dim3(DIM / 128, gy), 256, SMEMG7>>>(
            p_oh, p_wh + wo_o, p_x, nullptr,
            MROWS, DIM, DIM, nullptr, p_mod, 2 * DIM, 2);

        ln_mod_kernel<<<MROWS, 256>>>(p_x, p_xnh, ln2_g + l * DIM, ln2_b + l * DIM,
                                      p_mod, 3 * DIM, 4 * DIM);

        mma_gemm7_kernel<<<dim3(MLPD / 128, gy), 256, SMEMG7>>>(
            p_xnh, p_wh + wm1_o, nullptr, p_hh,
            MROWS, MLPD, DIM, nullptr, nullptr, 0, 1);
        mma_gemm7_kernel<<<dim3(DIM / 128, gy), 256, SMEMG7>>>(
            p_hh, p_wh + wm2_o, p_x, nullptr,
            MROWS, DIM, MLPD, nullptr, p_mod, 5 * DIM, 2);
    }

    final_ln_kernel<<<BATCH * NPATCH, 256>>>(fn_g, fn_b);
    // final projection fused with unpatchify scatter (epi 4)
    mma_gemm7_kernel<<<dim3(PCH / 128, 16), 256, SMEMG7>>>(
        p_xnh, p_wh + OFF_FIN, out, nullptr,
        BATCH * NPATCH, PCH, DIM, b_final, nullptr, 0, 4);
}

// round 17
// speedup vs baseline: 1.0658x; 1.0658x over previous
#include <cuda_runtime.h>
#include <cuda_bf16.h>
#include <cuda_fp16.h>
#include <math.h>

// ---------------- problem constants ----------------
#define BATCH   4
#define TEXT    64
#define NTOK    321
#define DIM     1024
#define HEADS   16
#define HD      64
#define MLPD    4096
#define NPATCH  256
#define PCH     768
#define TDIM    256
#define NLAYERS 2
#define VOCAB   50000
#define IMG     256
#define MROWS   (BATCH*NTOK) // 1284
#define DD      (DIM*DIM)
#define NPAD    384

typedef unsigned short u16;
typedef unsigned int u32;

// ---------------- scratch ----------------
__device__ float g_x  [MROWS*DIM];
__device__ float g_qkv[MROWS*3*DIM];
__device__ float g_t1raw[BATCH*DIM];
__device__ float g_t1 [BATCH*DIM];
__device__ float g_mod[BATCH*6*DIM];
__device__ float g_ropec[NPAD*HD];
__device__ float g_ropes[NPAD*HD];

// fp16 activation buffers
__device__ __align__(16) u16 g_xn_h[MROWS*DIM];
__device__ __align__(16) u16 g_hh  [MROWS*MLPD];
__device__ __align__(16) u16 g_o_h [MROWS*DIM];
__device__ __align__(16) u16 g_im_h[BATCH*NPATCH*PCH];

// fp16 weights
#define OFF_PATCH 0
#define SZ_PATCH  (DIM*PCH)
#define OFF_QKV   (OFF_PATCH+SZ_PATCH)
#define SZ_QKV    (NLAYERS*3*DD)
#define OFF_WO    (OFF_QKV+SZ_QKV)
#define SZ_WO     (NLAYERS*DD)
#define OFF_WM1   (OFF_WO+SZ_WO)
#define SZ_WM     (NLAYERS*MLPD*DIM)
#define OFF_WM2   (OFF_WM1+SZ_WM)
#define OFF_FIN   (OFF_WM2+SZ_WM)
#define SZ_FIN    (PCH*DIM)
#define WTOTAL    (OFF_FIN+SZ_FIN)
__device__ __align__(16) u16 g_w_h[WTOTAL];

// ---------------- helpers ----------------
__device__ __forceinline__ void store_h(float v, u16* h, long idx) {
    h[idx] = __half_as_ushort(__float2half_rn(v));
}
__device__ __forceinline__ u16 fp16_hi(float v) {
    return __half_as_ushort(__float2half_rn(v));
}

// ---------------- RoPE tables ----------------
__global__ void rope_table_kernel() {
    int idx = blockIdx.x * blockDim.x + threadIdx.x;
    if (idx >= NPAD * HD) return;
    int d = idx & 63, n = idx >> 6;
    double fr = pow(10000.0, -((double)(d & 31)) / 32.0);
    double a = (double)n * fr;
    g_ropec[idx] = (float)cos(a);
    g_ropes[idx] = (float)sin(a);
}

// ---------------- mega weight conversion ----------------
__global__ void cvt_all_kernel(const float* __restrict__ Wp,
                               const float* __restrict__ Wq, const float* __restrict__ Wk,
                               const float* __restrict__ Wv, const float* __restrict__ Wo,
                               const float* __restrict__ Wm1, const float* __restrict__ Wm2,
                               const float* __restrict__ Wf) {
    long q = (long)blockIdx.x * blockDim.x + threadIdx.x;
    long nq = WTOTAL / 4;
    if (q >= nq) return;
    long idx = q * 4;
    const float* src;
    long sofs;
    if (idx < OFF_QKV) { src = Wp; sofs = idx; }
    else if (idx < OFF_WO) {
        long rel = idx - OFF_QKV;
        long l = rel / (3 * (long)DD);
        long r2 = rel % (3 * (long)DD);
        long which = r2 / DD;
        long inner = r2 % DD;
        src = (which == 0) ? Wq : (which == 1) ? Wk : Wv;
        sofs = l * DD + inner;
    } else if (idx < OFF_WM1) { src = Wo; sofs = idx - OFF_WO; }
    else if (idx < OFF_WM2) { src = Wm1; sofs = idx - OFF_WM1; }
    else if (idx < OFF_FIN) { src = Wm2; sofs = idx - OFF_WM2; }
    else { src = Wf; sofs = idx - OFF_FIN; }
    float4 v = *(const float4*)(src + sofs);
    ushort4 h;
    h.x = fp16_hi(v.x); h.y = fp16_hi(v.y); h.z = fp16_hi(v.z); h.w = fp16_hi(v.w);
    *(ushort4*)(g_w_h + idx) = h;
}

// ---------------- embeddings ----------------
__global__ void embed_text_cls_kernel(const int* __restrict__ tokens,
                                      const float* __restrict__ W_tok,
                                      const float* __restrict__ pos_text,
                                      const float* __restrict__ cls_tok) {
    int idx = blockIdx.x * blockDim.x + threadIdx.x;
    if (idx >= BATCH * 65 * DIM) return;
    int d = idx % DIM;
    int t = (idx / DIM) % 65;
    int b = idx / (DIM * 65);
    float v;
    if (t < TEXT) {
        int tok = tokens[b * TEXT + t];
        v = W_tok[(long)d * VOCAB + tok] + pos_text[t * DIM + d];
    } else v = cls_tok[d];
    g_x[(b * NTOK + t) * DIM + d] = v;
}

__global__ void im2col_kernel(const float* __restrict__ img) {
    int idx = blockIdx.x * blockDim.x + threadIdx.x;
    if (idx >= BATCH * NPATCH * PCH) return;
    int c = idx % PCH;
    int p = (idx / PCH) % NPATCH;
    int b = idx / (PCH * NPATCH);
    int ch = c / 256;
    int pr = (c / 16) % 16;
    int pc = c % 16;
    int hp = p / 16, wp = p % 16;
    float v = img[((b * 3 + ch) * IMG + hp * 16 + pr) * IMG + wp * 16 + pc];
    store_h(v, g_im_h, idx);
}

// ---------------- timestep embedding ----------------
__global__ void ts_a_kernel(const int* __restrict__ tsteps,
                            const float* __restrict__ W_t1, const float* __restrict__ b_t1) {
    __shared__ float sraw[TDIM];
    int b = blockIdx.y;
    int tid = threadIdx.x, lane = tid & 31, warp = tid >> 5;
    {
        int j = tid & 127;
        float f = expf(-logf(10000.0f) * (float)j / 128.0f);
        float a = (float)tsteps[b] * f;
        sraw[tid] = (tid < 128) ? cosf(a) : sinf(a);
    }
    __syncthreads();
#pragma unroll
    for (int r = 0; r < 4; r++) {
        int d = blockIdx.x * 32 + warp * 4 + r;
        const float4* w = (const float4*)(W_t1 + (long)d * TDIM);
        const float4* a4 = (const float4*)sraw;
        float s = 0.f;
#pragma unroll
        for (int it = 0; it < 2; it++) {
            float4 wv = w[it * 32 + lane];
            float4 av = a4[it * 32 + lane];
            s += wv.x * av.x + wv.y * av.y + wv.z * av.z + wv.w * av.w;
        }
#pragma unroll
        for (int o = 16; o > 0; o >>= 1) s += __shfl_xor_sync(0xffffffffu, s, o);
        if (lane == 0) {
            s += b_t1[d];
            g_t1raw[b * DIM + d] = s / (1.0f + expf(-s));
        }
    }
}

__global__ void ts_b_kernel(const float* __restrict__ W_t2, const float* __restrict__ b_t2) {
    int b = blockIdx.y;
    int tid = threadIdx.x, lane = tid & 31, warp = tid >> 5;
    const float4* a4 = (const float4*)(g_t1raw + b * DIM);
#pragma unroll
    for (int r = 0; r < 4; r++) {
        int d = blockIdx.x * 32 + warp * 4 + r;
        const float4* w = (const float4*)(W_t2 + (long)d * DIM);
        float s = 0.f;
#pragma unroll
        for (int it = 0; it < 8; it++) {
            float4 wv = w[it * 32 + lane];
            float4 av = a4[it * 32 + lane];
            s += wv.x * av.x + wv.y * av.y + wv.z * av.z + wv.w * av.w;
        }
#pragma unroll
        for (int o = 16; o > 0; o >>= 1) s += __shfl_xor_sync(0xffffffffu, s, o);
        if (lane == 0) {
            s += b_t2[d];
            g_t1[b * DIM + d] = s / (1.0f + expf(-s));
        }
    }
}

// ---------------- adaLN modulation ----------------
__global__ void ada_kernel(const float* __restrict__ W, const float* __restrict__ bias) {
    int tid = threadIdx.x, lane = tid & 31, warp = tid >> 5;
#pragma unroll
    for (int r = 0; r < 4; r++) {
        int row = blockIdx.x * 32 + warp * 4 + r;
        const float4* w = (const float4*)(W + (long)row * DIM);
        float a0 = 0.f, a1 = 0.f, a2 = 0.f, a3 = 0.f;
#pragma unroll
        for (int it = 0; it < 8; it++) {
            float4 wv = w[it * 32 + lane];
            float4 v0 = *(const float4*)&g_t1[0 * DIM + it * 128 + lane * 4];
            float4 v1 = *(const float4*)&g_t1[1 * DIM + it * 128 + lane * 4];
            float4 v2 = *(const float4*)&g_t1[2 * DIM + it * 128 + lane * 4];
            float4 v3 = *(const float4*)&g_t1[3 * DIM + it * 128 + lane * 4];
            a0 += wv.x * v0.x + wv.y * v0.y + wv.z * v0.z + wv.w * v0.w;
            a1 += wv.x * v1.x + wv.y * v1.y + wv.z * v1.z + wv.w * v1.w;
            a2 += wv.x * v2.x + wv.y * v2.y + wv.z * v2.z + wv.w * v2.w;
            a3 += wv.x * v3.x + wv.y * v3.y + wv.z * v3.z + wv.w * v3.w;
        }
#pragma unroll
        for (int o = 16; o > 0; o >>= 1) {
            a0 += __shfl_xor_sync(0xffffffffu, a0, o);
            a1 += __shfl_xor_sync(0xffffffffu, a1, o);
            a2 += __shfl_xor_sync(0xffffffffu, a2, o);
            a3 += __shfl_xor_sync(0xffffffffu, a3, o);
        }
        if (lane == 0) {
            float bs = bias[row];
            g_mod[0 * 6 * DIM + row] = a0 + bs;
            g_mod[1 * 6 * DIM + row] = a1 + bs;
            g_mod[2 * 6 * DIM + row] = a2 + bs;
            g_mod[3 * 6 * DIM + row] = a3 + bs;
        }
    }
}

// ---------------- MMA primitives ----------------
__device__ __forceinline__ void cp16(u32 dst, const void* src, bool valid) {
    int sz = valid ? 16 : 0;
    asm volatile("cp.async.ca.shared.global [%0], [%1], 16, %2;\n" :: "r"(dst), "l"(src), "r"(sz));
}
__device__ __forceinline__ void cp_commit() { asm volatile("cp.async.commit_group;\n"); }
__device__ __forceinline__ void cp_wait0() { asm volatile("cp.async.wait_group 0;\n"); }
__device__ __forceinline__ void cp_wait1() { asm volatile("cp.async.wait_group 1;\n"); }

__device__ __forceinline__ void ldsm4(u32& r0, u32& r1, u32& r2, u32& r3, u32 addr) {
    asm volatile("ldmatrix.sync.aligned.m8n8.x4.shared.b16 {%0,%1,%2,%3}, [%4];\n"
                 : "=r"(r0), "=r"(r1), "=r"(r2), "=r"(r3) : "r"(addr));
}
__device__ __forceinline__ void ldsm4t(u32& r0, u32& r1, u32& r2, u32& r3, u32 addr) {
    asm volatile("ldmatrix.sync.aligned.m8n8.x4.trans.shared.b16 {%0,%1,%2,%3}, [%4];\n"
                 : "=r"(r0), "=r"(r1), "=r"(r2), "=r"(r3) : "r"(addr));
}

__device__ __forceinline__ void mma16816h(float* c, const u32* a, const u32* b) {
    asm volatile(
        "mma.sync.aligned.m16n8k16.row.col.f32.f16.f16.f32 "
        "{%0,%1,%2,%3}, {%4,%5,%6,%7}, {%8,%9}, {%0,%1,%2,%3};\n"
        : "+f"(c[0]), "+f"(c[1]), "+f"(c[2]), "+f"(c[3])
        : "r"(a[0]), "r"(a[1]), "r"(a[2]), "r"(a[3]), "r"(b[0]), "r"(b[1]));
}

// ---------------- tensor-core GEMM: fp16 x fp16, 64x128 tile ----------------
// epi: 0 = fp32 C (+bias); 1 = gelu -> fp16; 2 = fp32 C += gate*acc
// epi 3: patch embed -> g_x (bias = pos_img); epi 4: final scatter
__global__ __launch_bounds__(256) void mma_gemm7_kernel(
        const u16* __restrict__ Ah, const u16* __restrict__ Wh,
        float* __restrict__ C, u16* __restrict__ Oh,
        int M, int Nt, int K,
        const float* __restrict__ bias,
        const float* __restrict__ gate, int gate_ofs, int epi) {
    constexpr u32 RS  = 144;
    constexpr u32 SA  = 64 * RS;
    constexpr u32 SW  = 128 * RS;
    constexpr u32 WHI = SA;
    constexpr u32 STG = SA + SW;

    extern __shared__ char smem[];
    u32 sbase = (u32)__cvta_generic_to_shared(smem);

    int tid = threadIdx.x, lane = tid & 31, warp = tid >> 5;
    int wm = warp >> 2, wn = warp & 3;
    int row0 = blockIdx.y * 64, col0 = blockIdx.x * 128;

    float acc[2][4][4];
#pragma unroll
    for (int i = 0; i < 2; i++)
#pragma unroll
        for (int j = 0; j < 4; j++)
#pragma unroll
            for (int t = 0; t < 4; t++) acc[i][j][t] = 0.0f;

    u32 a_off = (lane & 15) * RS + (lane >> 4) * 16;
    u32 w_off = (((lane >> 4) & 1) * 8 + (lane & 7)) * RS + ((lane >> 3) & 1) * 16;

    auto stage_load = [&](int stage, int k0) {
        u32 sb = sbase + stage * STG;
#pragma unroll
        for (int c0 = 0; c0 < 1536; c0 += 256) {
            int c = c0 + tid;
            const u16* src;
            u32 dofs;
            int idx;
            bool isA;
            if (c < 512) { src = Ah; dofs = 0;   idx = c;       isA = true; }
            else         { src = Wh; dofs = WHI; idx = c - 512; isA = false; }
            int row = idx >> 3, q = idx & 7;
            long grow = isA ? (long)(row0 + row) : (long)(col0 + row);
            const void* s = src + grow * K + k0 + q * 8;
            cp16(sb + dofs + row * RS + q * 16, s, !isA || grow < M);
        }
    };

    int KT = K >> 6;
    stage_load(0, 0);
    cp_commit();

    for (int kt = 0; kt < KT; kt++) {
        if (kt + 1 < KT) {
            stage_load((kt + 1) & 1, (kt + 1) << 6);
            cp_commit();
            cp_wait1();
        } else {
            cp_wait0();
        }
        __syncthreads();

        u32 sb = sbase + (u32)(kt & 1) * STG;
#pragma unroll
        for (int s = 0; s < 4; s++) {
            u32 ah[2][4];
#pragma unroll
            for (int mt = 0; mt < 2; mt++) {
                u32 aaddr = sb + (wm * 32 + mt * 16) * RS + s * 32 + a_off;
                ldsm4(ah[mt][0], ah[mt][1], ah[mt][2], ah[mt][3], aaddr);
            }
            u32 bh[2][4];
#pragma unroll
            for (int ntp = 0; ntp < 2; ntp++) {
                u32 waddr = sb + WHI + (wn * 32 + ntp * 16) * RS + s * 32 + w_off;
                ldsm4(bh[ntp][0], bh[ntp][1], bh[ntp][2], bh[ntp][3], waddr);
            }
#pragma unroll
            for (int mt = 0; mt < 2; mt++)
#pragma unroll
                for (int nt = 0; nt < 4; nt++) {
                    const u32* Bh = &bh[nt >> 1][(nt & 1) * 2];
                    mma16816h(acc[mt][nt], ah[mt], Bh);
                }
        }
        __syncthreads();
    }

#pragma unroll
    for (int mt = 0; mt < 2; mt++)
#pragma unroll
        for (int nt = 0; nt < 4; nt++)
#pragma unroll
            for (int half = 0; half < 2; half++) {
                int row = row0 + wm * 32 + mt * 16 + (lane >> 2) + half * 8;
                if (row >= M) continue;
#pragma unroll
                for (int jj = 0; jj < 2; jj++) {
                    int col = col0 + wn * 32 + nt * 8 + (lane & 3) * 2 + jj;
                    float v = acc[mt][nt][half * 2 + jj];
                    long idx = (long)row * Nt + col;
                    if (epi == 0) {
                        if (bias) v += bias[col];
                        C[idx] = v;
                    } else if (epi == 1) {
                        float gu = 0.5f * v * (1.0f + erff(v * 0.70710678118654752f));
                        store_h(gu, Oh, idx);
                    } else if (epi == 2) {
                        int b = row / NTOK;
                        C[idx] += gate[b * 6 * DIM + gate_ofs + col] * v;
                    } else if (epi == 3) {
                        int b = row >> 8, p = row & 255;
                        C[(long)(b * NTOK + 65 + p) * DIM + col] = v + bias[p * DIM + col];
                    } else {
                        int b = row >> 8, p = row & 255;
                        int ch = col >> 8, pr = (col >> 4) & 15, pc = col & 15;
                        int hp = p >> 4, wp = p & 15;
                        C[((long)(b * 3 + ch) * IMG + hp * 16 + pr) * IMG + wp * 16 + pc] = v + bias[col];
                    }
                }
            }
}

// ---------------- layernorm + adaLN modulation ----------------
__global__ void ln_mod_kernel(const float* __restrict__ x,
                              u16* __restrict__ outh,
                              const float* __restrict__ g, const float* __restrict__ beta,
                              const float* __restrict__ mod, int sh_ofs, int sc_ofs) {
    int row = blockIdx.x;
    int b = row / NTOK;
    const float* xr = x + (long)row * DIM;
    __shared__ float red[256];
    int tid = threadIdx.x;
    float local[4];
    float s = 0.0f;
#pragma unroll
    for (int i = 0; i < 4; i++) { local[i] = xr[tid + i * 256]; s += local[i]; }
    red[tid] = s; __syncthreads();
    for (int o = 128; o > 0; o >>= 1) { if (tid < o) red[tid] += red[tid + o]; __syncthreads(); }
    float mean = red[0] * (1.0f / DIM);
    __syncthreads();
    float s2 = 0.0f;
#pragma unroll
    for (int i = 0; i < 4; i++) { float d = local[i] - mean; s2 += d * d; }
    red[tid] = s2; __syncthreads();
    for (int o = 128; o > 0; o >>= 1) { if (tid < o) red[tid] += red[tid + o]; __syncthreads(); }
    float inv = rsqrtf(red[0] * (1.0f / DIM) + 1e-5f);
#pragma unroll
    for (int i = 0; i < 4; i++) {
        int d = tid + i * 256;
        float v = (local[i] - mean) * inv * g[d] + beta[d];
        v = v * (1.0f + mod[b * 6 * DIM + sc_ofs + d]) + mod[b * 6 * DIM + sh_ofs + d];
        store_h(v, outh, (long)row * DIM + d);
    }
}

__global__ void final_ln_kernel(const float* __restrict__ g, const float* __restrict__ beta) {
    int p = blockIdx.x % NPATCH;
    int b = blockIdx.x / NPATCH;
    const float* xr = g_x + (long)(b * NTOK + 65 + p) * DIM;
    __shared__ float red[256];
    int tid = threadIdx.x;
    float local[4];
    float s = 0.0f;
#pragma unroll
    for (int i = 0; i < 4; i++) { local[i] = xr[tid + i * 256]; s += local[i]; }
    red[tid] = s; __syncthreads();
    for (int o = 128; o > 0; o >>= 1) { if (tid < o) red[tid] += red[tid + o]; __syncthreads(); }
    float mean = red[0] * (1.0f / DIM);
    __syncthreads();
    float s2 = 0.0f;
#pragma unroll
    for (int i = 0; i < 4; i++) { float d = local[i] - mean; s2 += d * d; }
    red[tid] = s2; __syncthreads();
    for (int o = 128; o > 0; o >>= 1) { if (tid < o) red[tid] += red[tid + o]; __syncthreads(); }
    float inv = rsqrtf(red[0] * (1.0f / DIM) + 1e-5f);
#pragma unroll
    for (int i = 0; i < 4; i++) {
        int d = tid + i * 256;
        float v = (local[i] - mean) * inv * g[d] + beta[d];
        store_h(v, g_xn_h, (long)blockIdx.x * DIM + d);
    }
}

// ---------------- flash attention v5: fp32 QKV in, single-fp16 QK + fp16 AV HMMA ----------------
#define FAB_QS   0                        // q fp32 stage [64][68] = 17408 B
#define FAB_KS   (64*68*4)                // k/v fp32 stage [32][68] = 8704 B
#define FAB_QH   (FAB_KS + 32*68*4)       // 26112: q fp16, 64 x 72 u16
#define FAB_KH   (FAB_QH + 64*144)        // 35328: k/v fp16, 32 x 72 u16
#define FAB_S    (FAB_KH + 32*144)        // 39936: S fp32 [64][352]
#define FAB_P    (FAB_S + 64*352*4)       // 130048: P fp16 [64][360]
#define FAB_TOT  (FAB_P + 64*360*2)       // 176128

__global__ __launch_bounds__(256) void flash_attn5_kernel(
        const float* __restrict__ qkv, u16* __restrict__ oh) {
    extern __shared__ char smraw[];
    u32 sbase = (u32)__cvta_generic_to_shared(smraw);
    float* qs = (float*)(smraw + FAB_QS);
    float* ks = (float*)(smraw + FAB_KS);
    float* S  = (float*)(smraw + FAB_S);
    u16* qh16 = (u16*)(smraw + FAB_QH);
    u16* kh16 = (u16*)(smraw + FAB_KH);
    u16* p16  = (u16*)(smraw + FAB_P);

    int tile = blockIdx.x;
    int bh = blockIdx.y;
    int h = bh % HEADS, b = bh / HEADS;
    int tid = threadIdx.x, lane = tid & 31, warp = tid >> 5;

    // ---- load Q (fp32) ----
    for (int i = tid; i < 64 * 64; i += 256) {
        int r = i >> 6, d = i & 63;
        int grow = tile * 64 + r;
        float v = 0.f;
        if (grow < NTOK) v = qkv[(long)(b * NTOK + grow) * 3072 + h * HD + d];
        qs[r * 68 + d] = v;
    }
    __syncthreads();
    // ---- RoPE Q -> single fp16 ----
#pragma unroll
    for (int t = 0; t < 16; t++) {
        int i = tid + t * 256;
        int r = i >> 6, d = i & 63;
        int grow = tile * 64 + r;
        float x = qs[r * 68 + d];
        float pr = (d < 32) ? -qs[r * 68 + 2 * d + 1] : qs[r * 68 + 2 * (d - 32)];
        float v = x * g_ropec[grow * HD + d] + pr * g_ropes[grow * HD + d];
        qh16[r * 72 + d] = __half_as_ushort(__float2half_rn(v));
    }
    __syncthreads();

    // ---- QK^T via HMMA: warps 4x2 over 64x32 chunk ----
    int wm = warp >> 1, wn = warp & 1;
    u32 a_off = (lane & 15) * 144 + (lane >> 4) * 16;
    u32 w_off = (((lane >> 4) & 1) * 8 + (lane & 7)) * 144 + ((lane >> 3) & 1) * 16;

    for (int c = 0; c < 11; c++) {
        for (int i = tid; i < 32 * 64; i += 256) {
            int j = i >> 6, d = i & 63;
            int krow = c * 32 + j;
            float v = 0.f;
            if (krow < NTOK) v = qkv[(long)(b * NTOK + krow) * 3072 + DIM + h * HD + d];
            ks[j * 68 + d] = v;
        }
        __syncthreads();
#pragma unroll
        for (int t = 0; t < 8; t++) {
            int i = tid + t * 256;
            int j = i >> 6, d = i & 63;
            float x = ks[j * 68 + d];
            float pr = (d < 32) ? -ks[j * 68 + 2 * d + 1] : ks[j * 68 + 2 * (d - 32)];
            int krow = c * 32 + j;
            float v = x * g_ropec[krow * HD + d] + pr * g_ropes[krow * HD + d];
            kh16[j * 72 + d] = __half_as_ushort(__float2half_rn(v));
        }
        __syncthreads();

        float accq[2][4];
#pragma unroll
        for (int n = 0; n < 2; n++)
#pragma unroll
            for (int t = 0; t < 4; t++) accq[n][t] = 0.f;
#pragma unroll
        for (int s = 0; s < 4; s++) {
            u32 ah[4], bk[4];
            u32 aaddr = sbase + FAB_QH + wm * 16 * 144 + s * 32 + a_off;
            ldsm4(ah[0], ah[1], ah[2], ah[3], aaddr);
            u32 baddr = sbase + FAB_KH + wn * 16 * 144 + s * 32 + w_off;
            ldsm4(bk[0], bk[1], bk[2], bk[3], baddr);
            mma16816h(accq[0], ah, bk + 0);
            mma16816h(accq[1], ah, bk + 2);
        }
#pragma unroll
        for (int nt = 0; nt < 2; nt++)
#pragma unroll
            for (int half = 0; half < 2; half++)
#pragma unroll
                for (int jj = 0; jj < 2; jj++) {
                    int row = wm * 16 + (lane >> 2) + half * 8;
                    int colL = wn * 16 + nt * 8 + (lane & 3) * 2 + jj;
                    int kg = c * 32 + colL;
                    S[row * 352 + c * 32 + colL] =
                        (kg < NTOK) ? accq[nt][half * 2 + jj] * 0.125f : -1e30f;
                }
        __syncthreads();
    }

    // ---- softmax; write P fp16 with invr folded ----
#pragma unroll
    for (int r8 = 0; r8 < 8; r8++) {
        float* Sr = &S[(warp * 8 + r8) * 352];
        float mx = -1e30f;
#pragma unroll
        for (int k = 0; k < 11; k++) mx = fmaxf(mx, Sr[lane + k * 32]);
#pragma unroll
        for (int o = 16; o > 0; o >>= 1) mx = fmaxf(mx, __shfl_xor_sync(0xffffffffu, mx, o));
        float sum = 0.f;
        float ev[11];
#pragma unroll
        for (int k = 0; k < 11; k++) {
            ev[k] = __expf(Sr[lane + k * 32] - mx);
            sum += ev[k];
        }
#pragma unroll
        for (int o = 16; o > 0; o >>= 1) sum += __shfl_xor_sync(0xffffffffu, sum, o);
        float inv = 1.0f / sum;
        u16* Pr = &p16[(warp * 8 + r8) * 360];
#pragma unroll
        for (int k = 0; k < 11; k++)
            Pr[lane + k * 32] = __half_as_ushort(__float2half_rn(ev[k] * inv));
    }
    __syncthreads();

    // ---- AV via HMMA: warps 4x2 (wm rows 16, wn cols 32) ----
    float accv[4][4];
#pragma unroll
    for (int n = 0; n < 4; n++)
#pragma unroll
        for (int t = 0; t < 4; t++) accv[n][t] = 0.f;

    u32 p_off = (lane & 15) * 720 + (lane >> 4) * 16;

    for (int c = 0; c < 11; c++) {
        // load V fp32 -> fp16 smem
        for (int i = tid; i < 32 * 64; i += 256) {
            int j = i >> 6, d = i & 63;
            int vrow = c * 32 + j;
            float v = 0.f;
            if (vrow < NTOK) v = qkv[(long)(b * NTOK + vrow) * 3072 + 2 * DIM + h * HD + d];
            kh16[j * 72 + d] = __half_as_ushort(__float2half_rn(v));
        }
        __syncthreads();
#pragma unroll
        for (int s = 0; s < 2; s++) {
            u32 pa[4];
            u32 paddr = sbase + FAB_P + (u32)(wm * 16) * 720 + (u32)(c * 32 + s * 16) * 2 + p_off;
            ldsm4(pa[0], pa[1], pa[2], pa[3], paddr);
#pragma unroll
            for (int nn = 0; nn < 2; nn++) {
                u32 vb[4];
                u32 vaddr = sbase + FAB_KH + (u32)(s * 16 + (lane & 15)) * 144
                            + (u32)(wn * 32 + nn * 16 + (lane >> 4) * 8) * 2;
                ldsm4t(vb[0], vb[1], vb[2], vb[3], vaddr);
                mma16816h(accv[nn * 2 + 0], pa, vb + 0);
                mma16816h(accv[nn * 2 + 1], pa, vb + 2);
            }
        }
        __syncthreads();
    }

    // ---- epilogue ----
#pragma unroll
    for (int nt = 0; nt < 4; nt++)
#pragma unroll
        for (int half = 0; half < 2; half++) {
            int rowL = wm * 16 + (lane >> 2) + half * 8;
            int grow = tile * 64 + rowL;
            if (grow >= NTOK) continue;
#pragma unroll
            for (int jj = 0; jj < 2; jj++) {
                int col = wn * 32 + nt * 8 + (lane & 3) * 2 + jj;
                store_h(accv[nt][half * 2 + jj], oh,
                        (long)(b * NTOK + grow) * DIM + h * HD + col);
            }
        }
}

// ---------------- host launch ----------------
static void* symaddr_raw(const void* sym) {
    void* p = nullptr;
    cudaGetSymbolAddress(&p, sym);
    return p;
}

#define SMEMG7 (2 * (64 * 144 + 128 * 144))   // 55296

extern "C" void kernel_launch(void* const* d_in, const int* in_sizes, int n_in,
                              void* d_out, int out_size) {
    const float* noisy    = (const float*)d_in[0];
    const int*   tokens   = (const int*)  d_in[1];
    const int*   tsteps   = (const int*)  d_in[2];
    const float* W_tok    = (const float*)d_in[3];
    const float* pos_text = (const float*)d_in[4];
    const float* W_patch  = (const float*)d_in[5];
    const float* pos_img  = (const float*)d_in[6];
    const float* cls_tok  = (const float*)d_in[7];
    const float* W_t1     = (const float*)d_in[8];
    const float* b_t1     = (const float*)d_in[9];
    const float* W_t2     = (const float*)d_in[10];
    const float* b_t2     = (const float*)d_in[11];
    const float* ln1_g    = (const float*)d_in[12];
    const float* ln1_b    = (const float*)d_in[13];
    const float* Wq       = (const float*)d_in[14];
    const float* Wk       = (const float*)d_in[15];
    const float* Wv       = (const float*)d_in[16];
    const float* Wo       = (const float*)d_in[17];
    const float* ln2_g    = (const float*)d_in[18];
    const float* ln2_b    = (const float*)d_in[19];
    const float* Wm1      = (const float*)d_in[20];
    const float* Wm2      = (const float*)d_in[21];
    const float* Wada     = (const float*)d_in[22];
    const float* b_ada    = (const float*)d_in[23];
    const float* fn_g     = (const float*)d_in[24];
    const float* fn_b     = (const float*)d_in[25];
    const float* W_final  = (const float*)d_in[26];
    const float* b_final  = (const float*)d_in[27];
    float* out = (float*)d_out;

    float* p_x    = (float*)symaddr_raw(g_x);
    float* p_qkv  = (float*)symaddr_raw(g_qkv);
    float* p_mod  = (float*)symaddr_raw(g_mod);
    u16* p_wh     = (u16*)symaddr_raw(g_w_h);
    u16* p_xnh    = (u16*)symaddr_raw(g_xn_h);
    u16* p_hh     = (u16*)symaddr_raw(g_hh);
    u16* p_oh     = (u16*)symaddr_raw(g_o_h);
    u16* p_imh    = (u16*)symaddr_raw(g_im_h);

    static bool attr_set = false;
    if (!attr_set) {
        cudaFuncSetAttribute(mma_gemm7_kernel, cudaFuncAttributeMaxDynamicSharedMemorySize, SMEMG7);
        cudaFuncSetAttribute(flash_attn5_kernel, cudaFuncAttributeMaxDynamicSharedMemorySize, FAB_TOT);
        attr_set = true;
    }

    im2col_kernel<<<(BATCH * NPATCH * PCH + 255) / 256, 256>>>(noisy);               // 0
    cvt_all_kernel<<<(WTOTAL / 4 + 511) / 512, 512>>>(W_patch, Wq, Wk, Wv, Wo, Wm1, Wm2, W_final); // 1
    ts_a_kernel<<<dim3(32, BATCH), 256>>>(tsteps, W_t1, b_t1);                        // 2
    // patch projection fused with pos_img add -> g_x (epi 3)
    mma_gemm7_kernel<<<dim3(DIM / 128, 16), 256, SMEMG7>>>(
        p_imh, p_wh + OFF_PATCH,
        p_x, nullptr, BATCH * NPATCH, DIM, PCH, pos_img, nullptr, 0, 3);              // 3
    rope_table_kernel<<<(NPAD * HD + 255) / 256, 256>>>();                            // 4
    ts_b_kernel<<<dim3(32, BATCH), 256>>>(W_t2, b_t2);                                // 5
    embed_text_cls_kernel<<<(BATCH * 65 * DIM + 255) / 256, 256>>>(tokens, W_tok, pos_text, cls_tok);

    int gy = (MROWS + 63) / 64;   // 21

    for (int l = 0; l < NLAYERS; l++) {
        long wqkv_o = OFF_QKV + (long)l * 3 * DD;
        long wo_o   = OFF_WO + (long)l * DD;
        long wm1_o  = OFF_WM1 + (long)l * MLPD * DIM;
        long wm2_o  = OFF_WM2 + (long)l * DIM * MLPD;
        const float* Wada_l = Wada + (long)l * 6 * DIM * DIM;
        const float* bada_l = b_ada + (long)l * 6 * DIM;

        ada_kernel<<<192, 256>>>(Wada_l, bada_l);

        ln_mod_kernel<<<MROWS, 256>>>(p_x, p_xnh, ln1_g + l * DIM, ln1_b + l * DIM,
                                      p_mod, 0, DIM);

        mma_gemm7_kernel<<<dim3(3 * DIM / 128, gy), 256, SMEMG7>>>(
            p_xnh, p_wh + wqkv_o, p_qkv, nullptr,
            MROWS, 3 * DIM, DIM, nullptr, nullptr, 0, 0);

        flash_attn5_kernel<<<dim3(6, BATCH * HEADS), 256, FAB_TOT>>>(p_qkv, p_oh);

        mma_gemm7_kernel<<<dim3(DIM / 128, gy), 256, SMEMG7>>>(
            p_oh, p_wh + wo_o, p_x, nullptr,
            MROWS, DIM, DIM, nullptr, p_mod, 2 * DIM, 2);

        ln_mod_kernel<<<MROWS, 256>>>(p_x, p_xnh, ln2_g + l * DIM, ln2_b + l * DIM,
                                      p_mod, 3 * DIM, 4 * DIM);

        mma_gemm7_kernel<<<dim3(MLPD / 128, gy), 256, SMEMG7>>>(
            p_xnh, p_wh + wm1_o, nullptr, p_hh,
            MROWS, MLPD, DIM, nullptr, nullptr, 0, 1);
        mma_gemm7_kernel<<<dim3(DIM / 128, gy), 256, SMEMG7>>>(
            p_hh, p_wh + wm2_o, p_x, nullptr,
            MROWS, DIM, MLPD, nullptr, p_mod, 5 * DIM, 2);
    }

    final_ln_kernel<<<BATCH * NPATCH, 256>>>(fn_g, fn_b);
    // final projection fused with unpatchify scatter (epi 4)
    mma_gemm7_kernel<<<dim3(PCH / 128, 16), 256, SMEMG7>>>(
        p_xnh, p_wh + OFF_FIN, out, nullptr,
        BATCH * NPATCH, PCH, DIM, b_final, nullptr, 0, 4);
}